// round 1
// baseline (speedup 1.0000x reference)
#include <cuda_runtime.h>
#include <cstdint>

// Problem constants (fixed by the reference)
#define B_ 16
#define H_ 100
#define W_ 100
#define C_ 256
#define R_ 128
#define P_ 7

// One CTA per (b, r, py, px) output cell. 64 threads, each does 4 channels
// via float4 -> four independent LDG.128 (MLP=4), one STG.128.
__global__ __launch_bounds__(64) void roi_pool_kernel(
    const float* __restrict__ fm,   // [B, H, W, C]
    const int*   __restrict__ rois, // [B, R, 4]  (x, y, h, w)
    float*       __restrict__ out)  // [B, R, P, P, C]
{
    int idx = blockIdx.x;
    const int px = idx % P_; idx /= P_;
    const int py = idx % P_; idx /= P_;
    const int r  = idx % R_; idx /= R_;
    const int b  = idx;

    const int4 roi = __ldg((const int4*)(rois + ((size_t)b * R_ + r) * 4));
    const int x = roi.x, y = roi.y, h = roi.z, w = roi.w;

    // y axis: src = (py+0.5)/P * h - 0.5, clipped to [0, h-1]
    const float hf = (float)h;
    float sy = ((float)py + 0.5f) * (1.0f / P_) * hf - 0.5f;
    sy = fminf(fmaxf(sy, 0.0f), hf - 1.0f);
    int   y0 = (int)floorf(sy);
    const float fy = sy - (float)y0;
    y0 += y;
    const int y1 = min(y0 + 1, y + h - 1);

    // x axis
    const float wf = (float)w;
    float sx = ((float)px + 0.5f) * (1.0f / P_) * wf - 0.5f;
    sx = fminf(fmaxf(sx, 0.0f), wf - 1.0f);
    int   x0 = (int)floorf(sx);
    const float fx = sx - (float)x0;
    x0 += x;
    const int x1 = min(x0 + 1, x + w - 1);

    const size_t base_b = (size_t)b * H_ * W_ * C_;
    const float4* p00 = (const float4*)(fm + base_b + ((size_t)y0 * W_ + x0) * C_);
    const float4* p01 = (const float4*)(fm + base_b + ((size_t)y0 * W_ + x1) * C_);
    const float4* p10 = (const float4*)(fm + base_b + ((size_t)y1 * W_ + x0) * C_);
    const float4* p11 = (const float4*)(fm + base_b + ((size_t)y1 * W_ + x1) * C_);

    const int c4 = threadIdx.x;   // 64 threads * 4 channels = 256

    const float4 a = __ldg(p00 + c4);
    const float4 bq = __ldg(p01 + c4);
    const float4 c = __ldg(p10 + c4);
    const float4 d = __ldg(p11 + c4);

    float4 o;
    {
        float top = a.x + (bq.x - a.x) * fx;
        float bot = c.x + (d.x  - c.x) * fx;
        o.x = top + (bot - top) * fy;
    }
    {
        float top = a.y + (bq.y - a.y) * fx;
        float bot = c.y + (d.y  - c.y) * fx;
        o.y = top + (bot - top) * fy;
    }
    {
        float top = a.z + (bq.z - a.z) * fx;
        float bot = c.z + (d.z  - c.z) * fx;
        o.z = top + (bot - top) * fy;
    }
    {
        float top = a.w + (bq.w - a.w) * fx;
        float bot = c.w + (d.w  - c.w) * fx;
        o.w = top + (bot - top) * fy;
    }

    float4* op = (float4*)(out + (((((size_t)b * R_ + r) * P_ + py) * P_ + px) * C_));
    op[c4] = o;
}

extern "C" void kernel_launch(void* const* d_in, const int* in_sizes, int n_in,
                              void* d_out, int out_size)
{
    const float* fm   = (const float*)d_in[0];
    const int*   rois = (const int*)d_in[1];
    float*       out  = (float*)d_out;

    const int nblocks = B_ * R_ * P_ * P_;  // 100352
    roi_pool_kernel<<<nblocks, 64>>>(fm, rois, out);
}

// round 2
// speedup vs baseline: 1.3163x; 1.3163x over previous
#include <cuda_runtime.h>
#include <cstdint>

// Problem constants (fixed by the reference)
#define B_ 16
#define H_ 100
#define W_ 100
#define C_ 256
#define R_ 128
#define P_ 7

struct CellPtrs {
    const float4 *p00, *p01, *p10, *p11;
    float4 *op;
    float fx, fy;
};

__device__ __forceinline__ CellPtrs cell_setup(
    int cell, const float* __restrict__ fm, const int* __restrict__ rois,
    float* __restrict__ out, int c4)
{
    int idx = cell;
    const int px = idx % P_; idx /= P_;
    const int py = idx % P_; idx /= P_;
    const int r  = idx % R_; idx /= R_;
    const int b  = idx;

    const int4 roi = __ldg((const int4*)(rois + ((size_t)b * R_ + r) * 4));
    const int x = roi.x, y = roi.y, h = roi.z, w = roi.w;

    // y axis: src = (py+0.5)/P * h - 0.5, clipped to [0, h-1]
    const float hf = (float)h;
    float sy = ((float)py + 0.5f) * (1.0f / P_) * hf - 0.5f;
    sy = fminf(fmaxf(sy, 0.0f), hf - 1.0f);
    int   y0 = (int)floorf(sy);
    const float fy = sy - (float)y0;
    y0 += y;
    const int y1 = min(y0 + 1, y + h - 1);

    // x axis
    const float wf = (float)w;
    float sx = ((float)px + 0.5f) * (1.0f / P_) * wf - 0.5f;
    sx = fminf(fmaxf(sx, 0.0f), wf - 1.0f);
    int   x0 = (int)floorf(sx);
    const float fx = sx - (float)x0;
    x0 += x;
    const int x1 = min(x0 + 1, x + w - 1);

    const float* base = fm + (size_t)b * (H_ * W_ * C_);

    CellPtrs cp;
    cp.p00 = (const float4*)(base + ((size_t)y0 * W_ + x0) * C_) + c4;
    cp.p01 = (const float4*)(base + ((size_t)y0 * W_ + x1) * C_) + c4;
    cp.p10 = (const float4*)(base + ((size_t)y1 * W_ + x0) * C_) + c4;
    cp.p11 = (const float4*)(base + ((size_t)y1 * W_ + x1) * C_) + c4;
    cp.op  = (float4*)(out + (size_t)cell * C_) + c4;
    cp.fx = fx;
    cp.fy = fy;
    return cp;
}

__device__ __forceinline__ float4 lerp4(float4 a, float4 b, float4 c, float4 d,
                                        float fx, float fy)
{
    float4 o;
    float top, bot;
    top = a.x + (b.x - a.x) * fx;  bot = c.x + (d.x - c.x) * fx;  o.x = top + (bot - top) * fy;
    top = a.y + (b.y - a.y) * fx;  bot = c.y + (d.y - c.y) * fx;  o.y = top + (bot - top) * fy;
    top = a.z + (b.z - a.z) * fx;  bot = c.z + (d.z - c.z) * fx;  o.z = top + (bot - top) * fy;
    top = a.w + (b.w - a.w) * fx;  bot = c.w + (d.w - c.w) * fx;  o.w = top + (bot - top) * fy;
    return o;
}

// 256-thread CTAs; each CTA handles 8 consecutive output cells; each thread
// handles a float4 channel-group of 2 cells -> 8 independent LDG.128 in flight.
__global__ __launch_bounds__(256) void roi_pool_kernel(
    const float* __restrict__ fm,   // [B, H, W, C]
    const int*   __restrict__ rois, // [B, R, 4]  (x, y, h, w)
    float*       __restrict__ out)  // [B, R, P, P, C]
{
    const int tid = threadIdx.x;
    const int c4  = tid & 63;           // float4 channel group (0..63)
    const int sub = tid >> 6;           // 0..3
    const int cell0 = blockIdx.x * 8 + sub * 2;
    const int cell1 = cell0 + 1;

    const CellPtrs A = cell_setup(cell0, fm, rois, out, c4);
    const CellPtrs Bc = cell_setup(cell1, fm, rois, out, c4);

    // Issue all 8 loads before any consumption (max MLP).
    const float4 a0 = __ldg(A.p00);
    const float4 b0 = __ldg(A.p01);
    const float4 c0 = __ldg(A.p10);
    const float4 d0 = __ldg(A.p11);
    const float4 a1 = __ldg(Bc.p00);
    const float4 b1 = __ldg(Bc.p01);
    const float4 c1 = __ldg(Bc.p10);
    const float4 d1 = __ldg(Bc.p11);

    const float4 o0 = lerp4(a0, b0, c0, d0, A.fx, A.fy);
    const float4 o1 = lerp4(a1, b1, c1, d1, Bc.fx, Bc.fy);

    // Streaming stores: output is write-once; keep L2 for feature-map reuse.
    __stcs(A.op, o0);
    __stcs(Bc.op, o1);
}

extern "C" void kernel_launch(void* const* d_in, const int* in_sizes, int n_in,
                              void* d_out, int out_size)
{
    const float* fm   = (const float*)d_in[0];
    const int*   rois = (const int*)d_in[1];
    float*       out  = (float*)d_out;

    const int ncells  = B_ * R_ * P_ * P_;  // 100352
    const int nblocks = ncells / 8;         // 12544
    roi_pool_kernel<<<nblocks, 256>>>(fm, rois, out);
}

// round 3
// speedup vs baseline: 1.4960x; 1.1365x over previous
#include <cuda_runtime.h>
#include <cstdint>

// Problem constants (fixed by the reference)
#define B_ 16
#define H_ 100
#define W_ 100
#define C_ 256
#define R_ 128
#define P_ 7
#define CELLS (P_ * P_)   // 49

// One CTA per ROI. Phase 1: threads 0..48 compute the bilinear tuple for one
// output cell each into smem. Phase 2: 256 threads = (4 cell-lanes) x (64
// float4 channel groups) sweep all 49 cells with a strided loop.
__global__ __launch_bounds__(256) void roi_pool_kernel(
    const float* __restrict__ fm,   // [B, H, W, C]
    const int*   __restrict__ rois, // [B, R, 4]  (x, y, h, w)
    float*       __restrict__ out)  // [B, R, P, P, C]
{
    __shared__ int4   s_off[CELLS];   // (off00, off01, off10, off11) in floats
    __shared__ float2 s_fr[CELLS];    // (fx, fy)

    const int roi_idx = blockIdx.x;        // b*R + r
    const int b = roi_idx >> 7;            // R_ = 128
    const int tid = threadIdx.x;

    if (tid < CELLS) {
        const int4 roi = __ldg((const int4*)(rois + (size_t)roi_idx * 4));
        const int x = roi.x, y = roi.y, h = roi.z, w = roi.w;

        const int py = tid / P_;
        const int px = tid - py * P_;

        // y axis: src = (py+0.5)/P * h - 0.5, clipped to [0, h-1]
        const float hf = (float)h;
        float sy = ((float)py + 0.5f) * (1.0f / P_) * hf - 0.5f;
        sy = fminf(fmaxf(sy, 0.0f), hf - 1.0f);
        int   y0 = (int)floorf(sy);
        const float fy = sy - (float)y0;
        y0 += y;
        const int y1 = min(y0 + 1, y + h - 1);

        // x axis
        const float wf = (float)w;
        float sx = ((float)px + 0.5f) * (1.0f / P_) * wf - 0.5f;
        sx = fminf(fmaxf(sx, 0.0f), wf - 1.0f);
        int   x0 = (int)floorf(sx);
        const float fx = sx - (float)x0;
        x0 += x;
        const int x1 = min(x0 + 1, x + w - 1);

        s_off[tid] = make_int4((y0 * W_ + x0) * C_,
                               (y0 * W_ + x1) * C_,
                               (y1 * W_ + x0) * C_,
                               (y1 * W_ + x1) * C_);
        s_fr[tid] = make_float2(fx, fy);
    }
    __syncthreads();

    const int c4  = tid & 63;     // float4 channel group 0..63
    const int sub = tid >> 6;     // cell lane 0..3

    const float4* base  = (const float4*)(fm + (size_t)b * (H_ * W_ * C_)) + c4;
    float4*       obase = (float4*)(out + (size_t)roi_idx * (CELLS * C_)) + c4;

    #pragma unroll 4
    for (int cell = sub; cell < CELLS; cell += 4) {
        const int4   off = s_off[cell];   // broadcast within warp
        const float2 fr  = s_fr[cell];

        const float4 a = __ldg(base + (off.x >> 2));
        const float4 bb = __ldg(base + (off.y >> 2));
        const float4 c = __ldg(base + (off.z >> 2));
        const float4 d = __ldg(base + (off.w >> 2));

        const float fx = fr.x, fy = fr.y;
        float4 o;
        float top, bot;
        top = a.x + (bb.x - a.x) * fx;  bot = c.x + (d.x - c.x) * fx;  o.x = top + (bot - top) * fy;
        top = a.y + (bb.y - a.y) * fx;  bot = c.y + (d.y - c.y) * fx;  o.y = top + (bot - top) * fy;
        top = a.z + (bb.z - a.z) * fx;  bot = c.z + (d.z - c.z) * fx;  o.z = top + (bot - top) * fy;
        top = a.w + (bb.w - a.w) * fx;  bot = c.w + (d.w - c.w) * fx;  o.w = top + (bot - top) * fy;

        __stcs(obase + cell * (C_ / 4), o);
    }
}

extern "C" void kernel_launch(void* const* d_in, const int* in_sizes, int n_in,
                              void* d_out, int out_size)
{
    const float* fm   = (const float*)d_in[0];
    const int*   rois = (const int*)d_in[1];
    float*       out  = (float*)d_out;

    roi_pool_kernel<<<B_ * R_, 256>>>(fm, rois, out);
}